// round 11
// baseline (speedup 1.0000x reference)
#include <cuda_runtime.h>
#include <cuda_bf16.h>

// QuantizedGRU: T=512, B=1024, H=12, Q7 fixed point (scale 128).
// Round 11 = Round 8 body with ILP-2: each 16-lane group carries TWO
// batches (independent register chains, shared weight registers), so one
// batch's STS->LDS broadcast latency is filled by the other's arithmetic.
// Geometry: 128 blocks x 64 threads (4 groups x 2 batches = 8/block).
// All arithmetic in the exact x128 scaled-integer fp32 domain (bit-exact).

#define TT  512
#define BB  1024
#define INV 0.0078125f
#define MAGIC 12582912.0f            /* 1.5 * 2^23 */
#define XROW 516                     /* padded x row: 512 + 4 OOB slots */

typedef unsigned long long u64;

__device__ __forceinline__ float rne(float v) {
    return __fadd_rn(__fadd_rn(v, MAGIC), -MAGIC);
}
__device__ __forceinline__ float rneq(float v) {
    return fminf(fmaxf(rne(v), -32768.0f), 32767.0f);
}
__device__ __forceinline__ float qs(float v) {   // quantized weight, scaled
    return rneq(__fmul_rn(v, 128.0f));
}
__device__ __forceinline__ float qr(float v) {   // quantized weight, real
    return __fmul_rn(qs(v), INV);
}
__device__ __forceinline__ u64 pk2(float lo, float hi) {
    u64 r;
    asm("mov.b64 %0, {%1, %2};" : "=l"(r) : "f"(lo), "f"(hi));
    return r;
}
__device__ __forceinline__ void fma2(u64& d, u64 a, u64 b) {
    asm("fma.rn.f32x2 %0, %1, %2, %0;" : "+l"(d) : "l"(a), "l"(b));
}
__device__ __forceinline__ u64 add2(u64 a, u64 b) {
    u64 r;
    asm("add.rn.f32x2 %0, %1, %2;" : "=l"(r) : "l"(a), "l"(b));
    return r;
}
__device__ __forceinline__ u64 mul2(u64 a, u64 b) {
    u64 r;
    asm("mul.rn.f32x2 %0, %1, %2;" : "=l"(r) : "l"(a), "l"(b));
    return r;
}
__device__ __forceinline__ void unpk2(float& lo, float& hi, u64 v) {
    asm("mov.b64 {%0, %1}, %2;" : "=f"(lo), "=f"(hi) : "l"(v));
}
__device__ __forceinline__ float hsum2(u64 v) {
    float lo, hi;
    unpk2(lo, hi, v);
    return __fadd_rn(lo, hi);
}
__device__ __forceinline__ unsigned smem_u32(const void* p) {
    unsigned a;
    asm("{ .reg .u64 t; cvta.to.shared.u64 t, %1; cvt.u32.u64 %0, t; }"
        : "=r"(a) : "l"(p));
    return a;
}

// ---------------------------------------------------------------------------
// 128 blocks x 64 threads: 4 groups/block, 2 batches/group.
// lanes 0-11: gate triple r (W_hh rows r, r+12, r+24)
// lanes 12,13: FCNN rows (W1 rows 0-2 / 3-5), output pipelined 1 step behind
// lanes 14,15: zero weights (same instruction stream)
// ---------------------------------------------------------------------------
__global__ void __launch_bounds__(64, 1) gru_kernel(
        const float* __restrict__ x,
        const float* __restrict__ wih_raw, const float* __restrict__ whh_raw,
        const float* __restrict__ bih_raw, const float* __restrict__ bhh_raw,
        const float* __restrict__ w1_raw,  const float* __restrict__ b1_raw,
        const float* __restrict__ w2_raw,  const float* __restrict__ b2_raw,
        float* __restrict__ out) {
    __shared__ __align__(16) float xs[8 * XROW];       // [batch][t], padded
    __shared__ __align__(16) float hbuf[8 * 16];       // h broadcast rows

    const int tid = threadIdx.x;
    const int r   = tid & 15;
    const int g   = tid >> 4;             // group 0..3
    const int bbA = 2 * g, bbB = 2 * g + 1;
    const int b0  = blockIdx.x << 3;

    // stage x transposed: xs[bj][t] = x[t][b0+bj]; zero the 4 pad slots
    for (int i = tid; i < TT * 8; i += 64) {
        const int t  = i >> 3;
        const int bj = i & 7;
        xs[bj * XROW + t] = x[t * BB + b0 + bj];
    }
    { const int bj = tid >> 3, sl = tid & 7;          // 64 thr: 8 rows x 8
      if (sl < 4) xs[bj * XROW + TT + sl] = 0.0f; }

    // ---- per-lane constants (shared by both batches) ----
    u64 wA[6], wB[6], wC[6];
    u64 ws01 = 0, cb01M = pk2(-MAGIC, -MAGIC);
    float ws2 = 0.f, cb2 = 0.f;
    float KC = __fmul_rn(-MAGIC, INV);
    float w2a = 0.f, w2b = 0.f, w2cS = 0.f;            // w2cS: SCALED weight
#pragma unroll
    for (int k = 0; k < 6; ++k) { wA[k] = 0; wB[k] = 0; wC[k] = 0; }

    if (r < 12) {
        const float* pA = whh_raw + r * 12;            // r-gate row
        const float* pB = whh_raw + (r + 12) * 12;     // z-gate row
        const float* pC = whh_raw + (r + 24) * 12;     // n-gate row
#pragma unroll
        for (int k = 0; k < 6; ++k) {
            wA[k] = pk2(qr(pA[2 * k]), qr(pA[2 * k + 1]));
            wB[k] = pk2(qr(pB[2 * k]), qr(pB[2 * k + 1]));
            wC[k] = pk2(qr(pC[2 * k]), qr(pC[2 * k + 1]));
        }
        ws01  = pk2(qs(wih_raw[r]), qs(wih_raw[r + 12]));
        cb01M = pk2((qs(bih_raw[r])      + qs(bhh_raw[r]))      - MAGIC,
                    (qs(bih_raw[r + 12]) + qs(bhh_raw[r + 12])) - MAGIC);
        ws2 = qs(wih_raw[r + 24]);
        cb2 = qs(bih_raw[r + 24]);
        KC  = __fmul_rn(qs(bhh_raw[r + 24]) - MAGIC, INV);
    } else if (r < 14) {
        const int r0 = (r - 12) * 3;
#pragma unroll
        for (int j = 0; j < 3; ++j) {
            const float* p = w1_raw + (r0 + j) * 12;
            u64* w = (j == 0) ? wA : ((j == 1) ? wB : wC);
#pragma unroll
            for (int k = 0; k < 6; ++k)
                w[k] = pk2(qr(p[2 * k]), qr(p[2 * k + 1]));
        }
        cb01M = pk2(qs(b1_raw[r0 + 0]) - MAGIC,
                    qs(b1_raw[r0 + 1]) - MAGIC);
        KC   = __fmul_rn(qs(b1_raw[r0 + 2]) - MAGIC, INV);
        w2a  = qr(w2_raw[r0 + 0]);
        w2b  = qr(w2_raw[r0 + 1]);
        w2cS = qs(w2_raw[r0 + 2]);   // scaled, since qCr is real-domain
    }
    const float b2sM = qs(b2_raw[0]) - MAGIC;
    const float K64  = 64.0f + 0.75f * MAGIC;   // exact
    const float MP   = MAGIC + 128.0f;
    const float MM   = MAGIC - 128.0f;
    const u64   M2   = pk2(MAGIC, MAGIC);

    __syncthreads();

    // ---- per-batch state ----
    u64 hpA[6], hpB[6];
#pragma unroll
    for (int k = 0; k < 6; ++k) { hpA[k] = 0; hpB[k] = 0; }
    float hMA = MAGIC, hMB = MAGIC;             // h + MAGIC, h0 = 0
    float* opA = out + (b0 + bbA) - BB;
    float* opB = out + (b0 + bbB) - BB;

    const unsigned xsaA = smem_u32(xs + bbA * XROW);
    const unsigned xsaB = xsaA + XROW * 4u;
    const unsigned hbaA = smem_u32(hbuf) + (bbA << 6);
    const unsigned hbaB = hbaA + 64u;
    const unsigned hstA = hbaA + (r << 2);
    const unsigned hstB = hbaB + (r << 2);

    float4 xqA = make_float4(0.f, 0.f, 0.f, 0.f);
    float4 xqB = xqA;

#pragma unroll 4
    for (int t = 0; t < 516; ++t) {
        if ((t & 3) == 0) {
            asm volatile("ld.shared.v4.f32 {%0,%1,%2,%3}, [%4];"
                : "=f"(xqA.x), "=f"(xqA.y), "=f"(xqA.z), "=f"(xqA.w)
                : "r"(xsaA + (unsigned)t * 4u));
            asm volatile("ld.shared.v4.f32 {%0,%1,%2,%3}, [%4];"
                : "=f"(xqB.x), "=f"(xqB.y), "=f"(xqB.z), "=f"(xqB.w)
                : "r"(xsaB + (unsigned)t * 4u));
        }
        const float xA = ((t & 3) == 0) ? xqA.x : ((t & 3) == 1) ? xqA.y :
                         ((t & 3) == 2) ? xqA.z : xqA.w;
        const float xB = ((t & 3) == 0) ? xqB.x : ((t & 3) == 1) ? xqB.y :
                         ((t & 3) == 2) ? xqB.z : xqB.w;

        // ii precompute (off critical path)
        const u64 i01A = add2(add2(mul2(pk2(xA, xA), ws01), M2), cb01M);
        const u64 i01B = add2(add2(mul2(pk2(xB, xB), ws01), M2), cb01M);
        float i0A, i1A, i0B, i1B;
        unpk2(i0A, i1A, i01A);
        unpk2(i0B, i1B, i01B);
        const float i2MA = __fadd_rn(__fadd_rn(__fmul_rn(xA, ws2), MAGIC), cb2);
        const float i2MB = __fadd_rn(__fadd_rn(__fmul_rn(xB, ws2), MAGIC), cb2);

        // ---- packed dots, batch A then B (independent; ptxas interleaves)
        u64 a0A = 0, a1A = 0, c0A = 0, c1A = 0, e0A = 0, e1A = 0;
        u64 a0B = 0, a1B = 0, c0B = 0, c1B = 0, e0B = 0, e1B = 0;
#pragma unroll
        for (int k = 0; k < 3; ++k) {
            fma2(a0A, hpA[k], wA[k]);     fma2(a0B, hpB[k], wA[k]);
            fma2(a1A, hpA[k + 3], wA[k + 3]); fma2(a1B, hpB[k + 3], wA[k + 3]);
            fma2(c0A, hpA[k], wC[k]);     fma2(c0B, hpB[k], wC[k]);
            fma2(c1A, hpA[k + 3], wC[k + 3]); fma2(c1B, hpB[k + 3], wC[k + 3]);
            fma2(e0A, hpA[k], wB[k]);     fma2(e0B, hpB[k], wB[k]);
            fma2(e1A, hpA[k + 3], wB[k + 3]); fma2(e1B, hpB[k + 3], wB[k + 3]);
        }
        const float sAA = __fadd_rn(hsum2(add2(a0A, a1A)), MAGIC);
        const float sCA = __fadd_rn(hsum2(add2(c0A, c1A)), MAGIC);
        const float sBA = __fadd_rn(hsum2(add2(e0A, e1A)), MAGIC);
        const float sAB = __fadd_rn(hsum2(add2(a0B, a1B)), MAGIC);
        const float sCB = __fadd_rn(hsum2(add2(c0B, c1B)), MAGIC);
        const float sBB = __fadd_rn(hsum2(add2(e0B, e1B)), MAGIC);

        const float vAMA = __fadd_rn(sAA, i0A);
        const float vBMA = __fadd_rn(sBA, i1A);
        const float qCrA = __fmaf_rn(INV, sCA, KC);
        const float vAMB = __fadd_rn(sAB, i0B);
        const float vBMB = __fadd_rn(sBB, i1B);
        const float qCrB = __fmaf_rn(INV, sCB, KC);

        // ---- gates, batch A ----
        const float rtMA = fminf(fmaxf(__fmaf_rn(0.25f, vAMA, K64), MAGIC), MP);
        const float ztMA = fminf(fmaxf(__fmaf_rn(0.25f, vBMA, K64), MAGIC), MP);
        const float rtA  = __fadd_rn(rtMA, -MAGIC);
        const float ztIA = __fmul_rn(__fadd_rn(ztMA, -MAGIC), INV);
        const float ntMA = fminf(fmaxf(__fmaf_rn(rtA, qCrA, i2MA), MM), MP);
        const float dA   = __fadd_rn(hMA, -ntMA);
        const float hnMA = __fmaf_rn(ztIA, dA, ntMA);
        const float hnA  = __fadd_rn(hnMA, -MAGIC);
        hMA = hnMA;

        // ---- gates, batch B ----
        const float rtMB = fminf(fmaxf(__fmaf_rn(0.25f, vAMB, K64), MAGIC), MP);
        const float ztMB = fminf(fmaxf(__fmaf_rn(0.25f, vBMB, K64), MAGIC), MP);
        const float rtB  = __fadd_rn(rtMB, -MAGIC);
        const float ztIB = __fmul_rn(__fadd_rn(ztMB, -MAGIC), INV);
        const float ntMB = fminf(fmaxf(__fmaf_rn(rtB, qCrB, i2MB), MM), MP);
        const float dB   = __fadd_rn(hMB, -ntMB);
        const float hnMB = __fmaf_rn(ztIB, dB, ntMB);
        const float hnB  = __fadd_rn(hnMB, -MAGIC);
        hMB = hnMB;

        // ---- broadcasts: STS both, then LDS both (R8 ordering) ----
        asm volatile("st.shared.b32 [%0], %1;" :: "r"(hstA), "f"(hnA) : "memory");
        asm volatile("st.shared.b32 [%0], %1;" :: "r"(hstB), "f"(hnB) : "memory");
        asm volatile("ld.shared.v2.u64 {%0,%1}, [%2];"
                     : "=l"(hpA[0]), "=l"(hpA[1]) : "r"(hbaA) : "memory");
        asm volatile("ld.shared.v2.u64 {%0,%1}, [%2];"
                     : "=l"(hpA[2]), "=l"(hpA[3]) : "r"(hbaA + 16u) : "memory");
        asm volatile("ld.shared.v2.u64 {%0,%1}, [%2];"
                     : "=l"(hpA[4]), "=l"(hpA[5]) : "r"(hbaA + 32u) : "memory");
        asm volatile("ld.shared.v2.u64 {%0,%1}, [%2];"
                     : "=l"(hpB[0]), "=l"(hpB[1]) : "r"(hbaB) : "memory");
        asm volatile("ld.shared.v2.u64 {%0,%1}, [%2];"
                     : "=l"(hpB[2]), "=l"(hpB[3]) : "r"(hbaB + 16u) : "memory");
        asm volatile("ld.shared.v2.u64 {%0,%1}, [%2];"
                     : "=l"(hpB[4]), "=l"(hpB[5]) : "r"(hbaB + 32u) : "memory");

        // ---- fcnn epilogues (after critical LDS; outputs for step t-1) ----
        {
            const float qa = __fadd_rn(fmaxf(vAMA, MAGIC), -MAGIC);
            const float qb = __fadd_rn(fmaxf(vBMA, MAGIC), -MAGIC);
            const float qc = fmaxf(qCrA, 0.0f);
            float pa = __fmaf_rn(qa, w2a,
                       __fmaf_rn(qb, w2b, __fmul_rn(qc, w2cS)));
            pa += __shfl_xor_sync(0xffffffffu, pa, 1);
            if (r == 12 && (unsigned)(t - 1) < 512u)
                opA[t * BB] = __fmul_rn(
                    __fadd_rn(__fadd_rn(pa, MAGIC), b2sM), INV);
        }
        {
            const float qa = __fadd_rn(fmaxf(vAMB, MAGIC), -MAGIC);
            const float qb = __fadd_rn(fmaxf(vBMB, MAGIC), -MAGIC);
            const float qc = fmaxf(qCrB, 0.0f);
            float pa = __fmaf_rn(qa, w2a,
                       __fmaf_rn(qb, w2b, __fmul_rn(qc, w2cS)));
            pa += __shfl_xor_sync(0xffffffffu, pa, 1);
            if (r == 12 && (unsigned)(t - 1) < 512u)
                opB[t * BB] = __fmul_rn(
                    __fadd_rn(__fadd_rn(pa, MAGIC), b2sM), INV);
        }
    }
}

// ---------------------------------------------------------------------------
extern "C" void kernel_launch(void* const* d_in, const int* in_sizes, int n_in,
                              void* d_out, int out_size) {
    const float* input = (const float*)d_in[0];
    const float* wih   = (const float*)d_in[1];
    const float* whh   = (const float*)d_in[2];
    const float* bih   = (const float*)d_in[3];
    const float* bhh   = (const float*)d_in[4];
    const float* w1    = (const float*)d_in[5];
    const float* b1    = (const float*)d_in[6];
    const float* w2    = (const float*)d_in[7];
    const float* b2    = (const float*)d_in[8];
    float* out = (float*)d_out;

    gru_kernel<<<128, 64>>>(input, wih, whh, bih, bhh,
                            w1, b1, w2, b2, out);
}

// round 12
// speedup vs baseline: 1.5568x; 1.5568x over previous
#include <cuda_runtime.h>
#include <cuda_bf16.h>

// QuantizedGRU: T=512, B=1024, H=12, Q7 fixed point (scale 128).
// Round 12 = Round 8 (proven 48.1us; 128 blocks x 128 thr, 1 warp/SMSP
// chip-wide) with ONE change: the FCNN epilogue (shfl + STG on the
// in-order MIO queue) is moved to the very END of the loop body, after
// the critical STS->LDS broadcast, so gates issue immediately after the
// dot sums and the broadcast is never queued behind fcnn MIO ops.
// All arithmetic in the exact x128 scaled-integer fp32 domain (bit-exact).

#define TT  512
#define BB  1024
#define INV 0.0078125f
#define MAGIC 12582912.0f            /* 1.5 * 2^23 */
#define XROW 516                     /* padded x row: 512 + 4 OOB slots */

typedef unsigned long long u64;

__device__ __forceinline__ float rne(float v) {
    return __fadd_rn(__fadd_rn(v, MAGIC), -MAGIC);
}
__device__ __forceinline__ float rneq(float v) {
    return fminf(fmaxf(rne(v), -32768.0f), 32767.0f);
}
__device__ __forceinline__ float qs(float v) {   // quantized weight, scaled
    return rneq(__fmul_rn(v, 128.0f));
}
__device__ __forceinline__ float qr(float v) {   // quantized weight, real
    return __fmul_rn(qs(v), INV);
}
__device__ __forceinline__ u64 pk2(float lo, float hi) {
    u64 r;
    asm("mov.b64 %0, {%1, %2};" : "=l"(r) : "f"(lo), "f"(hi));
    return r;
}
__device__ __forceinline__ void fma2(u64& d, u64 a, u64 b) {
    asm("fma.rn.f32x2 %0, %1, %2, %0;" : "+l"(d) : "l"(a), "l"(b));
}
__device__ __forceinline__ u64 add2(u64 a, u64 b) {
    u64 r;
    asm("add.rn.f32x2 %0, %1, %2;" : "=l"(r) : "l"(a), "l"(b));
    return r;
}
__device__ __forceinline__ u64 mul2(u64 a, u64 b) {
    u64 r;
    asm("mul.rn.f32x2 %0, %1, %2;" : "=l"(r) : "l"(a), "l"(b));
    return r;
}
__device__ __forceinline__ void unpk2(float& lo, float& hi, u64 v) {
    asm("mov.b64 {%0, %1}, %2;" : "=f"(lo), "=f"(hi) : "l"(v));
}
__device__ __forceinline__ float hsum2(u64 v) {
    float lo, hi;
    unpk2(lo, hi, v);
    return __fadd_rn(lo, hi);
}
__device__ __forceinline__ unsigned smem_u32(const void* p) {
    unsigned a;
    asm("{ .reg .u64 t; cvta.to.shared.u64 t, %1; cvt.u32.u64 %0, t; }"
        : "=r"(a) : "l"(p));
    return a;
}

// ---------------------------------------------------------------------------
// 128 blocks x 128 threads: 8 batches/block, 16 threads/batch.
// lanes 0-11: gate triple r (W_hh rows r, r+12, r+24)
// lanes 12,13: FCNN rows (W1 rows 0-2 / 3-5), output pipelined 1 step behind
// lanes 14,15: zero weights (same instruction stream)
// ---------------------------------------------------------------------------
__global__ void __launch_bounds__(128, 1) gru_kernel(
        const float* __restrict__ x,
        const float* __restrict__ wih_raw, const float* __restrict__ whh_raw,
        const float* __restrict__ bih_raw, const float* __restrict__ bhh_raw,
        const float* __restrict__ w1_raw,  const float* __restrict__ b1_raw,
        const float* __restrict__ w2_raw,  const float* __restrict__ b2_raw,
        float* __restrict__ out) {
    __shared__ __align__(16) float xs[8 * XROW];       // [batch][t], padded
    __shared__ __align__(16) float hbuf[8 * 16];       // h broadcast rows

    const int tid = threadIdx.x;
    const int r   = tid & 15;
    const int bb  = tid >> 4;
    const int b0  = blockIdx.x << 3;
    const int b   = b0 + bb;

    // stage x transposed: xs[bj][t] = x[t][b0+bj]; zero the 4 pad slots
    for (int i = tid; i < TT * 8; i += 128) {
        const int t  = i >> 3;
        const int bj = i & 7;
        xs[bj * XROW + t] = x[t * BB + b0 + bj];
    }
    if (tid < 32) xs[(tid >> 2) * XROW + TT + (tid & 3)] = 0.0f;

    // ---- per-lane constants ----
    u64 wA[6], wB[6], wC[6];
    u64 ws01 = 0, cb01M = pk2(-MAGIC, -MAGIC);
    float ws2 = 0.f, cb2 = 0.f;
    float KC = __fmul_rn(-MAGIC, INV);
    float w2a = 0.f, w2b = 0.f, w2cS = 0.f;            // w2cS: SCALED weight
#pragma unroll
    for (int k = 0; k < 6; ++k) { wA[k] = 0; wB[k] = 0; wC[k] = 0; }

    if (r < 12) {
        const float* pA = whh_raw + r * 12;            // r-gate row
        const float* pB = whh_raw + (r + 12) * 12;     // z-gate row
        const float* pC = whh_raw + (r + 24) * 12;     // n-gate row
#pragma unroll
        for (int k = 0; k < 6; ++k) {
            wA[k] = pk2(qr(pA[2 * k]), qr(pA[2 * k + 1]));
            wB[k] = pk2(qr(pB[2 * k]), qr(pB[2 * k + 1]));
            wC[k] = pk2(qr(pC[2 * k]), qr(pC[2 * k + 1]));
        }
        ws01  = pk2(qs(wih_raw[r]), qs(wih_raw[r + 12]));
        cb01M = pk2((qs(bih_raw[r])      + qs(bhh_raw[r]))      - MAGIC,
                    (qs(bih_raw[r + 12]) + qs(bhh_raw[r + 12])) - MAGIC);
        ws2 = qs(wih_raw[r + 24]);
        cb2 = qs(bih_raw[r + 24]);
        KC  = __fmul_rn(qs(bhh_raw[r + 24]) - MAGIC, INV);
    } else if (r < 14) {
        const int r0 = (r - 12) * 3;
#pragma unroll
        for (int j = 0; j < 3; ++j) {
            const float* p = w1_raw + (r0 + j) * 12;
            u64* w = (j == 0) ? wA : ((j == 1) ? wB : wC);
#pragma unroll
            for (int k = 0; k < 6; ++k)
                w[k] = pk2(qr(p[2 * k]), qr(p[2 * k + 1]));
        }
        cb01M = pk2(qs(b1_raw[r0 + 0]) - MAGIC,
                    qs(b1_raw[r0 + 1]) - MAGIC);
        KC   = __fmul_rn(qs(b1_raw[r0 + 2]) - MAGIC, INV);
        w2a  = qr(w2_raw[r0 + 0]);
        w2b  = qr(w2_raw[r0 + 1]);
        w2cS = qs(w2_raw[r0 + 2]);   // scaled, since qCr is real-domain
    }
    const float b2sM = qs(b2_raw[0]) - MAGIC;
    const float K64  = 64.0f + 0.75f * MAGIC;   // exact
    const float MP   = MAGIC + 128.0f;
    const float MM   = MAGIC - 128.0f;
    const u64   M2   = pk2(MAGIC, MAGIC);

    __syncthreads();

    u64 hp[6];
#pragma unroll
    for (int k = 0; k < 6; ++k) hp[k] = 0;
    float hM_own = MAGIC;                       // h + MAGIC, h0 = 0
    float* op    = out + b - BB;                // output for step t-1

    const unsigned xsa = smem_u32(xs + bb * XROW);
    const unsigned hba = smem_u32(hbuf) + (bb << 6);
    const unsigned hst = hba + (r << 2);

    float4 xq = make_float4(0.f, 0.f, 0.f, 0.f);

#pragma unroll 4
    for (int t = 0; t <= TT; ++t) {
        if ((t & 3) == 0) {
            asm volatile("ld.shared.v4.f32 {%0,%1,%2,%3}, [%4];"
                : "=f"(xq.x), "=f"(xq.y), "=f"(xq.z), "=f"(xq.w)
                : "r"(xsa + (unsigned)t * 4u));
        }
        const float xcur = ((t & 3) == 0) ? xq.x :
                           ((t & 3) == 1) ? xq.y :
                           ((t & 3) == 2) ? xq.z : xq.w;

        // ii precompute (off critical path); packed for r/z, scalar for n.
        const u64 i01 = add2(add2(mul2(pk2(xcur, xcur), ws01), M2), cb01M);
        float i0, i1;
        unpk2(i0, i1, i01);                     // true ints
        const float i2M = __fadd_rn(__fadd_rn(__fmul_rn(xcur, ws2), MAGIC), cb2);

        // ---- packed dots with h_{t-1} (two 3-deep chains per row) ----
        u64 a0 = 0, a1 = 0, c0 = 0, c1 = 0, e0 = 0, e1 = 0;
        fma2(a0, hp[0], wA[0]); fma2(a0, hp[1], wA[1]); fma2(a0, hp[2], wA[2]);
        fma2(a1, hp[3], wA[3]); fma2(a1, hp[4], wA[4]); fma2(a1, hp[5], wA[5]);
        fma2(c0, hp[0], wC[0]); fma2(c0, hp[1], wC[1]); fma2(c0, hp[2], wC[2]);
        fma2(c1, hp[3], wC[3]); fma2(c1, hp[4], wC[4]); fma2(c1, hp[5], wC[5]);
        fma2(e0, hp[0], wB[0]); fma2(e0, hp[1], wB[1]); fma2(e0, hp[2], wB[2]);
        fma2(e1, hp[3], wB[3]); fma2(e1, hp[4], wB[4]); fma2(e1, hp[5], wB[5]);
        const float sA = __fadd_rn(hsum2(add2(a0, a1)), MAGIC);  // rne(dA)+M
        const float sC = __fadd_rn(hsum2(add2(c0, c1)), MAGIC);
        const float sB = __fadd_rn(hsum2(add2(e0, e1)), MAGIC);

        const float vAM = __fadd_rn(sA, i0);        // ii_r + hh_r + M
        const float vBM = __fadd_rn(sB, i1);
        const float qCr = __fmaf_rn(INV, sC, KC);   // (rne(dC)+cC)/128, exact

        // ---- gates IMMEDIATELY (fused round-in-FMA), hM-form tail ----
        const float rtM = fminf(fmaxf(__fmaf_rn(0.25f, vAM, K64), MAGIC), MP);
        const float ztM = fminf(fmaxf(__fmaf_rn(0.25f, vBM, K64), MAGIC), MP);
        const float rt  = __fadd_rn(rtM, -MAGIC);
        const float ztI = __fmul_rn(__fadd_rn(ztM, -MAGIC), INV);  // zt/128
        const float ntM = fminf(fmaxf(__fmaf_rn(rt, qCr, i2M), MM), MP);
        const float d   = __fadd_rn(hM_own, -ntM);   // h - nt, exact
        const float hnM = __fmaf_rn(ztI, d, ntM);    // exact single rounding
        const float hn  = __fadd_rn(hnM, -MAGIC);
        hM_own = hnM;

        // ---- broadcast h_t: STS own slot, LDS packed pairs (R8 order) ----
        asm volatile("st.shared.b32 [%0], %1;" :: "r"(hst), "f"(hn) : "memory");
        asm volatile("ld.shared.v2.u64 {%0,%1}, [%2];"
                     : "=l"(hp[0]), "=l"(hp[1]) : "r"(hba) : "memory");
        asm volatile("ld.shared.v2.u64 {%0,%1}, [%2];"
                     : "=l"(hp[2]), "=l"(hp[3]) : "r"(hba + 16u) : "memory");
        asm volatile("ld.shared.v2.u64 {%0,%1}, [%2];"
                     : "=l"(hp[4]), "=l"(hp[5]) : "r"(hba + 32u) : "memory");

        // ---- fcnn epilogue LAST (lanes 12,13; output for step t-1) ----
        const float qa = __fadd_rn(fmaxf(vAM, MAGIC), -MAGIC);
        const float qb = __fadd_rn(fmaxf(vBM, MAGIC), -MAGIC);
        const float qc = fmaxf(qCr, 0.0f);
        float pa = __fmaf_rn(qa, w2a,
                   __fmaf_rn(qb, w2b, __fmul_rn(qc, w2cS)));
        pa += __shfl_xor_sync(0xffffffffu, pa, 1);
        if (r == 12 && (unsigned)(t - 1) < 512u)
            op[t * BB] = __fmul_rn(
                __fadd_rn(__fadd_rn(pa, MAGIC), b2sM), INV);
    }
}

// ---------------------------------------------------------------------------
extern "C" void kernel_launch(void* const* d_in, const int* in_sizes, int n_in,
                              void* d_out, int out_size) {
    const float* input = (const float*)d_in[0];
    const float* wih   = (const float*)d_in[1];
    const float* whh   = (const float*)d_in[2];
    const float* bih   = (const float*)d_in[3];
    const float* bhh   = (const float*)d_in[4];
    const float* w1    = (const float*)d_in[5];
    const float* b1    = (const float*)d_in[6];
    const float* w2    = (const float*)d_in[7];
    const float* b2    = (const float*)d_in[8];
    float* out = (float*)d_out;

    gru_kernel<<<BB / 8, 128>>>(input, wih, whh, bih, bhh,
                                w1, b1, w2, b2, out);
}

// round 13
// speedup vs baseline: 1.5780x; 1.0136x over previous
#include <cuda_runtime.h>
#include <cuda_bf16.h>

// QuantizedGRU: T=512, B=1024, H=12, Q7 fixed point (scale 128).
// Round 13 = Round 8 (proven 48.1us ordering) with the sigmoid gates
// rewritten via fma.rn.sat:
//   s  = sat(rn(v/512 + 0.5))            -- 1 op, == clip(0.25x+0.5,0,1)
//   rt = fma(s,128,M) - M                -- fused quantize (proven)
//   ztI= (sZ + 98304) - 98304            -- rne at 1/128 grain, == zt/128
// Path vAM->ntM: 28 -> 24 cyc; -3 issue ops/step. All arithmetic stays in
// the exact x128 scaled-integer fp32 domain (bit-exact; every rounding is
// a verified single-rounding with preserved ties-to-even parity).

#define TT  512
#define BB  1024
#define INV 0.0078125f
#define MAGIC 12582912.0f            /* 1.5 * 2^23 */
#define C7   98304.0f                /* 1.5 * 2^16: ulp = 1/128 */
#define XROW 516                     /* padded x row: 512 + 4 OOB slots */

typedef unsigned long long u64;

__device__ __forceinline__ float rne(float v) {
    return __fadd_rn(__fadd_rn(v, MAGIC), -MAGIC);
}
__device__ __forceinline__ float rneq(float v) {
    return fminf(fmaxf(rne(v), -32768.0f), 32767.0f);
}
__device__ __forceinline__ float qs(float v) {   // quantized weight, scaled
    return rneq(__fmul_rn(v, 128.0f));
}
__device__ __forceinline__ float qr(float v) {   // quantized weight, real
    return __fmul_rn(qs(v), INV);
}
__device__ __forceinline__ float satfma(float a, float b, float c) {
    float r;
    asm("fma.rn.sat.f32 %0, %1, %2, %3;" : "=f"(r) : "f"(a), "f"(b), "f"(c));
    return r;
}
__device__ __forceinline__ u64 pk2(float lo, float hi) {
    u64 r;
    asm("mov.b64 %0, {%1, %2};" : "=l"(r) : "f"(lo), "f"(hi));
    return r;
}
__device__ __forceinline__ void fma2(u64& d, u64 a, u64 b) {
    asm("fma.rn.f32x2 %0, %1, %2, %0;" : "+l"(d) : "l"(a), "l"(b));
}
__device__ __forceinline__ u64 add2(u64 a, u64 b) {
    u64 r;
    asm("add.rn.f32x2 %0, %1, %2;" : "=l"(r) : "l"(a), "l"(b));
    return r;
}
__device__ __forceinline__ u64 mul2(u64 a, u64 b) {
    u64 r;
    asm("mul.rn.f32x2 %0, %1, %2;" : "=l"(r) : "l"(a), "l"(b));
    return r;
}
__device__ __forceinline__ void unpk2(float& lo, float& hi, u64 v) {
    asm("mov.b64 {%0, %1}, %2;" : "=f"(lo), "=f"(hi) : "l"(v));
}
__device__ __forceinline__ float hsum2(u64 v) {
    float lo, hi;
    unpk2(lo, hi, v);
    return __fadd_rn(lo, hi);
}
__device__ __forceinline__ unsigned smem_u32(const void* p) {
    unsigned a;
    asm("{ .reg .u64 t; cvta.to.shared.u64 t, %1; cvt.u32.u64 %0, t; }"
        : "=r"(a) : "l"(p));
    return a;
}

// ---------------------------------------------------------------------------
// 128 blocks x 128 threads: 8 batches/block, 16 threads/batch.
// lanes 0-11: gate triple r (W_hh rows r, r+12, r+24)
// lanes 12,13: FCNN rows (W1 rows 0-2 / 3-5), output pipelined 1 step behind
// lanes 14,15: zero weights (same instruction stream)
// ---------------------------------------------------------------------------
__global__ void __launch_bounds__(128, 1) gru_kernel(
        const float* __restrict__ x,
        const float* __restrict__ wih_raw, const float* __restrict__ whh_raw,
        const float* __restrict__ bih_raw, const float* __restrict__ bhh_raw,
        const float* __restrict__ w1_raw,  const float* __restrict__ b1_raw,
        const float* __restrict__ w2_raw,  const float* __restrict__ b2_raw,
        float* __restrict__ out) {
    __shared__ __align__(16) float xs[8 * XROW];       // [batch][t], padded
    __shared__ __align__(16) float hbuf[8 * 16];       // h broadcast rows

    const int tid = threadIdx.x;
    const int r   = tid & 15;
    const int bb  = tid >> 4;
    const int b0  = blockIdx.x << 3;
    const int b   = b0 + bb;

    // stage x transposed: xs[bj][t] = x[t][b0+bj]; zero the 4 pad slots
    for (int i = tid; i < TT * 8; i += 128) {
        const int t  = i >> 3;
        const int bj = i & 7;
        xs[bj * XROW + t] = x[t * BB + b0 + bj];
    }
    if (tid < 32) xs[(tid >> 2) * XROW + TT + (tid & 3)] = 0.0f;

    // ---- per-lane constants ----
    u64 wA[6], wB[6], wC[6];
    u64 ws01 = 0, cb01M = pk2(-MAGIC, -MAGIC);
    float ws2 = 0.f, cb2 = 0.f;
    float KC = __fmul_rn(-MAGIC, INV);
    float w2a = 0.f, w2b = 0.f, w2cS = 0.f;            // w2cS: SCALED weight
#pragma unroll
    for (int k = 0; k < 6; ++k) { wA[k] = 0; wB[k] = 0; wC[k] = 0; }

    if (r < 12) {
        const float* pA = whh_raw + r * 12;            // r-gate row
        const float* pB = whh_raw + (r + 12) * 12;     // z-gate row
        const float* pC = whh_raw + (r + 24) * 12;     // n-gate row
#pragma unroll
        for (int k = 0; k < 6; ++k) {
            wA[k] = pk2(qr(pA[2 * k]), qr(pA[2 * k + 1]));
            wB[k] = pk2(qr(pB[2 * k]), qr(pB[2 * k + 1]));
            wC[k] = pk2(qr(pC[2 * k]), qr(pC[2 * k + 1]));
        }
        ws01  = pk2(qs(wih_raw[r]), qs(wih_raw[r + 12]));
        cb01M = pk2((qs(bih_raw[r])      + qs(bhh_raw[r]))      - MAGIC,
                    (qs(bih_raw[r + 12]) + qs(bhh_raw[r + 12])) - MAGIC);
        ws2 = qs(wih_raw[r + 24]);
        cb2 = qs(bih_raw[r + 24]);
        KC  = __fmul_rn(qs(bhh_raw[r + 24]) - MAGIC, INV);
    } else if (r < 14) {
        const int r0 = (r - 12) * 3;
#pragma unroll
        for (int j = 0; j < 3; ++j) {
            const float* p = w1_raw + (r0 + j) * 12;
            u64* w = (j == 0) ? wA : ((j == 1) ? wB : wC);
#pragma unroll
            for (int k = 0; k < 6; ++k)
                w[k] = pk2(qr(p[2 * k]), qr(p[2 * k + 1]));
        }
        cb01M = pk2(qs(b1_raw[r0 + 0]) - MAGIC,
                    qs(b1_raw[r0 + 1]) - MAGIC);
        KC   = __fmul_rn(qs(b1_raw[r0 + 2]) - MAGIC, INV);
        w2a  = qr(w2_raw[r0 + 0]);
        w2b  = qr(w2_raw[r0 + 1]);
        w2cS = qs(w2_raw[r0 + 2]);   // scaled, since qCr is real-domain
    }
    const float b2sM = qs(b2_raw[0]) - MAGIC;
    const float c512 = 0.001953125f;            // 1/512, exact
    const float KA   = -24575.5f;               // 0.5 - MAGIC/512, exact
    const float MP   = MAGIC + 128.0f;
    const float MM   = MAGIC - 128.0f;
    const u64   M2   = pk2(MAGIC, MAGIC);

    __syncthreads();

    u64 hp[6];
#pragma unroll
    for (int k = 0; k < 6; ++k) hp[k] = 0;
    float hM_own = MAGIC;                       // h + MAGIC, h0 = 0
    float* op    = out + b - BB;                // output for step t-1

    const unsigned xsa = smem_u32(xs + bb * XROW);
    const unsigned hba = smem_u32(hbuf) + (bb << 6);
    const unsigned hst = hba + (r << 2);

    float4 xq = make_float4(0.f, 0.f, 0.f, 0.f);

#pragma unroll 4
    for (int t = 0; t <= TT; ++t) {
        if ((t & 3) == 0) {
            asm volatile("ld.shared.v4.f32 {%0,%1,%2,%3}, [%4];"
                : "=f"(xq.x), "=f"(xq.y), "=f"(xq.z), "=f"(xq.w)
                : "r"(xsa + (unsigned)t * 4u));
        }
        const float xcur = ((t & 3) == 0) ? xq.x :
                           ((t & 3) == 1) ? xq.y :
                           ((t & 3) == 2) ? xq.z : xq.w;

        // ii precompute (off critical path); packed for r/z, scalar for n.
        const u64 i01 = add2(add2(mul2(pk2(xcur, xcur), ws01), M2), cb01M);
        float i0, i1;
        unpk2(i0, i1, i01);                     // true ints
        const float i2M = __fadd_rn(__fadd_rn(__fmul_rn(xcur, ws2), MAGIC), cb2);

        // ---- packed dots with h_{t-1} (two 3-deep chains per row) ----
        u64 a0 = 0, a1 = 0, c0 = 0, c1 = 0, e0 = 0, e1 = 0;
        fma2(a0, hp[0], wA[0]); fma2(a0, hp[1], wA[1]); fma2(a0, hp[2], wA[2]);
        fma2(a1, hp[3], wA[3]); fma2(a1, hp[4], wA[4]); fma2(a1, hp[5], wA[5]);
        fma2(c0, hp[0], wC[0]); fma2(c0, hp[1], wC[1]); fma2(c0, hp[2], wC[2]);
        fma2(c1, hp[3], wC[3]); fma2(c1, hp[4], wC[4]); fma2(c1, hp[5], wC[5]);
        fma2(e0, hp[0], wB[0]); fma2(e0, hp[1], wB[1]); fma2(e0, hp[2], wB[2]);
        fma2(e1, hp[3], wB[3]); fma2(e1, hp[4], wB[4]); fma2(e1, hp[5], wB[5]);
        const float sA = __fadd_rn(hsum2(add2(a0, a1)), MAGIC);  // rne(dA)+M
        const float sC = __fadd_rn(hsum2(add2(c0, c1)), MAGIC);
        const float sB = __fadd_rn(hsum2(add2(e0, e1)), MAGIC);

        const float vAM = __fadd_rn(sA, i0);        // ii_r + hh_r + M
        const float vBM = __fadd_rn(sB, i1);
        const float qCr = __fmaf_rn(INV, sC, KC);   // (rne(dC)+cC)/128, exact

        // ---- fcnn epilogue (R8 placement; output for step t-1) ----
        const float qa = __fadd_rn(fmaxf(vAM, MAGIC), -MAGIC);
        const float qb = __fadd_rn(fmaxf(vBM, MAGIC), -MAGIC);
        const float qc = fmaxf(qCr, 0.0f);
        float pa = __fmaf_rn(qa, w2a,
                   __fmaf_rn(qb, w2b, __fmul_rn(qc, w2cS)));
        pa += __shfl_xor_sync(0xffffffffu, pa, 1);
        if (r == 12 && (unsigned)(t - 1) < 512u)
            op[t * BB] = __fmul_rn(
                __fadd_rn(__fadd_rn(pa, MAGIC), b2sM), INV);

        // ---- gates: sat-fma sigmoids, fused rounds, hM-form tail ----
        const float sR  = satfma(vAM, c512, KA);    // clip(rn(v/512+.5),0,1)
        const float sZ  = satfma(vBM, c512, KA);
        const float rtM = __fmaf_rn(sR, 128.0f, MAGIC);  // rne(128 sR)+M
        const float rt  = __fadd_rn(rtM, -MAGIC);        // rt scaled int
        const float ztI = __fadd_rn(__fadd_rn(sZ, C7), -C7);  // zt/128
        const float ntM = fminf(fmaxf(__fmaf_rn(rt, qCr, i2M), MM), MP);
        const float d   = __fadd_rn(hM_own, -ntM);   // h - nt, exact
        const float hnM = __fmaf_rn(ztI, d, ntM);    // exact single rounding
        const float hn  = __fadd_rn(hnM, -MAGIC);
        hM_own = hnM;

        // ---- broadcast h_t: STS own slot, LDS packed pairs (R8 order) ----
        asm volatile("st.shared.b32 [%0], %1;" :: "r"(hst), "f"(hn) : "memory");
        asm volatile("ld.shared.v2.u64 {%0,%1}, [%2];"
                     : "=l"(hp[0]), "=l"(hp[1]) : "r"(hba) : "memory");
        asm volatile("ld.shared.v2.u64 {%0,%1}, [%2];"
                     : "=l"(hp[2]), "=l"(hp[3]) : "r"(hba + 16u) : "memory");
        asm volatile("ld.shared.v2.u64 {%0,%1}, [%2];"
                     : "=l"(hp[4]), "=l"(hp[5]) : "r"(hba + 32u) : "memory");
    }
}

// ---------------------------------------------------------------------------
extern "C" void kernel_launch(void* const* d_in, const int* in_sizes, int n_in,
                              void* d_out, int out_size) {
    const float* input = (const float*)d_in[0];
    const float* wih   = (const float*)d_in[1];
    const float* whh   = (const float*)d_in[2];
    const float* bih   = (const float*)d_in[3];
    const float* bhh   = (const float*)d_in[4];
    const float* w1    = (const float*)d_in[5];
    const float* b1    = (const float*)d_in[6];
    const float* w2    = (const float*)d_in[7];
    const float* b2    = (const float*)d_in[8];
    float* out = (float*)d_out;

    gru_kernel<<<BB / 8, 128>>>(input, wih, whh, bih, bhh,
                                w1, b1, w2, b2, out);
}